// round 2
// baseline (speedup 1.0000x reference)
#include <cuda_runtime.h>
#include <cuda_fp16.h>

// ---------------- problem constants ----------------
constexpr int cB   = 4;
constexpr int cCK  = 64;
constexpr int cTHW = 12960;   // 8*30*54
constexpr int cHW  = 1620;    // 30*54
constexpr int cN   = 8;
constexpr int cCV  = 512;
constexpr int cHWP = 1632;    // padded P row stride (16B-aligned rows for cp.async)
constexpr int cZCH = 24;      // chunks for deterministic Z reduction (12960/24=540)
constexpr int KT   = cTHW / 32;  // 405 k-tiles in readout GEMM

// ---------------- scratch (device globals: allocation-free) ----------------
__device__ float              g_S[(size_t)cB * cTHW * cHW];            // logits fp32
__device__ __align__(16) __half g_P[(size_t)cB * cTHW * cHWP + 4096];  // exp(s-M) fp16, padded
__device__ __align__(16) __half g_V[(size_t)cN * cCV * cTHW];          // values fp16
__device__ float              g_asq[cB * cTHW];
__device__ unsigned           g_M[cB * cHW];                           // column max, encoded key
__device__ float              g_Zp[cB * cZCH * cHW];                   // Z partials (deterministic)
__device__ float              g_Z[cB * cHW];                           // 1/Z

// order-preserving float <-> uint key (for exact, order-independent atomic max)
__device__ __forceinline__ unsigned fenc(float f) {
    unsigned u = __float_as_uint(f);
    return (u & 0x80000000u) ? ~u : (u | 0x80000000u);
}
__device__ __forceinline__ float fdec(unsigned k) {
    unsigned u = (k & 0x80000000u) ? (k ^ 0x80000000u) : ~k;
    return __uint_as_float(u);
}

// ---------------- k_init: reset column-max keys ----------------
__global__ void k_init() {
    int i = blockIdx.x * blockDim.x + threadIdx.x;
    if (i < cB * cHW) g_M[i] = 0u;  // below any real encoded key
}

// ---------------- k_asq: a_sq[b,t] = sum_c mk[b,c,t]^2 ----------------
__global__ void k_asq(const float* __restrict__ mk) {
    int i = blockIdx.x * blockDim.x + threadIdx.x;
    if (i >= cB * cTHW) return;
    int b = i / cTHW;
    int t = i - b * cTHW;
    const float* p = mk + (size_t)b * cCK * cTHW + t;
    float s = 0.f;
#pragma unroll 16
    for (int c = 0; c < cCK; c++) {
        float v = p[(size_t)c * cTHW];
        s = fmaf(v, v, s);
    }
    g_asq[i] = s;
}

// ---------------- k_vconv: mem_values fp32 -> fp16 ----------------
__global__ void k_vconv(const float* __restrict__ v) {
    size_t n4 = (size_t)cN * cCV * cTHW / 4;
    for (size_t i = (size_t)blockIdx.x * blockDim.x + threadIdx.x; i < n4;
         i += (size_t)gridDim.x * blockDim.x) {
        float4 f = ((const float4*)v)[i];
        __half2 h0 = __floats2half2_rn(f.x, f.y);
        __half2 h1 = __floats2half2_rn(f.z, f.w);
        ((__half2*)g_V)[2 * i]     = h0;
        ((__half2*)g_V)[2 * i + 1] = h1;
    }
}

// ---------------- k_logits: S = 0.25*ab - 0.125*asq, fused column max ----------------
__global__ void __launch_bounds__(256) k_logits(const float* __restrict__ mk,
                                                const float* __restrict__ qk) {
    __shared__ __align__(16) float MKs[64][68];  // [c][t_local]
    __shared__ __align__(16) float QS[64][68];   // [c][q_local]
    __shared__ unsigned smax[64];

    int tid = threadIdx.x;
    int b   = blockIdx.z;
    int t0  = blockIdx.y * 64;
    int q0  = blockIdx.x * 64;

    if (tid < 64) smax[tid] = 0u;

    const float* mkb = mk + (size_t)b * cCK * cTHW;
    const float* qkb = qk + (size_t)b * cCK * cHW;

#pragma unroll
    for (int j = 0; j < 4; j++) {
        int id  = tid + j * 256;        // 0..1023
        int c   = id >> 4;              // 0..63
        int col = (id & 15) * 4;        // 0..60
        float4 v = make_float4(0.f, 0.f, 0.f, 0.f);
        if (t0 + col < cTHW) v = *(const float4*)(mkb + (size_t)c * cTHW + t0 + col);
        *(float4*)&MKs[c][col] = v;
        float4 w = make_float4(0.f, 0.f, 0.f, 0.f);
        if (q0 + col < cHW) w = *(const float4*)(qkb + (size_t)c * cHW + q0 + col);
        *(float4*)&QS[c][col] = w;
    }
    __syncthreads();

    int ty = tid >> 4, tx = tid & 15;
    float acc[4][4];
#pragma unroll
    for (int i = 0; i < 4; i++)
#pragma unroll
        for (int j = 0; j < 4; j++) acc[i][j] = 0.f;

#pragma unroll 8
    for (int c = 0; c < 64; c++) {
        float av[4], bv[4];
        *(float4*)av = *(const float4*)&MKs[c][ty * 4];
        *(float4*)bv = *(const float4*)&QS[c][tx * 4];
#pragma unroll
        for (int i = 0; i < 4; i++)
#pragma unroll
            for (int j = 0; j < 4; j++) acc[i][j] = fmaf(av[i], bv[j], acc[i][j]);
    }

    int tbase = t0 + ty * 4;
    int qbase = q0 + tx * 4;
    bool qok  = (qbase < cHW);

    float asqv[4];
#pragma unroll
    for (int i = 0; i < 4; i++) {
        int t = tbase + i;
        asqv[i] = (t < cTHW) ? g_asq[b * cTHW + t] : 0.f;
    }

    float s[4][4];
#pragma unroll
    for (int i = 0; i < 4; i++)
#pragma unroll
        for (int j = 0; j < 4; j++) s[i][j] = 0.25f * acc[i][j] - 0.125f * asqv[i];

    if (qok) {
#pragma unroll
        for (int i = 0; i < 4; i++) {
            int t = tbase + i;
            if (t < cTHW) {
                float4 row = make_float4(s[i][0], s[i][1], s[i][2], s[i][3]);
                *(float4*)(g_S + ((size_t)b * cTHW + t) * cHW + qbase) = row;
            }
        }
        int nv = cTHW - tbase;
        if (nv > 4) nv = 4;
        if (nv > 0) {
#pragma unroll
            for (int j = 0; j < 4; j++) {
                float mx = s[0][j];
                for (int i = 1; i < nv; i++) mx = fmaxf(mx, s[i][j]);
                atomicMax(&smax[tx * 4 + j], fenc(mx));
            }
        }
    }
    __syncthreads();
    if (tid < 64 && q0 + tid < cHW) atomicMax(&g_M[b * cHW + q0 + tid], smax[tid]);
}

// ---------------- k_expsum: P = fp16(exp(s - M)); deterministic Z partials ----------------
__global__ void k_expsum() {
    int q = blockIdx.x * blockDim.x + threadIdx.x;
    if (q >= cHW) return;
    int b  = blockIdx.z;
    int ch = blockIdx.y;
    constexpr int CHN = cTHW / cZCH;  // 540
    int t0 = ch * CHN;

    float Mv = fdec(g_M[b * cHW + q]);
    const float* Sp = g_S + ((size_t)b * cTHW + t0) * cHW + q;
    __half* Pp      = g_P + ((size_t)b * cTHW + t0) * cHWP + q;

    float z = 0.f;
#pragma unroll 4
    for (int i = 0; i < CHN; i++) {
        float e = __expf(Sp[(size_t)i * cHW] - Mv);
        z += e;
        Pp[(size_t)i * cHWP] = __float2half_rn(e);
    }
    g_Zp[(b * cZCH + ch) * cHW + q] = z;
}

// ---------------- k_zred: invZ ----------------
__global__ void k_zred() {
    int i = blockIdx.x * blockDim.x + threadIdx.x;
    if (i >= cB * cHW) return;
    int b = i / cHW, q = i - b * cHW;
    float s = 0.f;
#pragma unroll
    for (int ch = 0; ch < cZCH; ch++) s += g_Zp[(b * cZCH + ch) * cHW + q];
    g_Z[i] = 1.0f / s;
}

// ---------------- k_gemm: out[n] = V16[n] @ P16[bm[n]] * invZ ----------------
__device__ __forceinline__ void cpasync16(void* dst, const void* src) {
    unsigned s = (unsigned)__cvta_generic_to_shared(dst);
    asm volatile("cp.async.cg.shared.global [%0], [%1], 16;\n" :: "r"(s), "l"(src));
}
__device__ __forceinline__ void ldsm_x4(unsigned& r0, unsigned& r1, unsigned& r2, unsigned& r3,
                                        const void* p) {
    unsigned a = (unsigned)__cvta_generic_to_shared(p);
    asm volatile("ldmatrix.sync.aligned.m8n8.x4.shared.b16 {%0,%1,%2,%3}, [%4];\n"
                 : "=r"(r0), "=r"(r1), "=r"(r2), "=r"(r3) : "r"(a));
}
__device__ __forceinline__ void ldsm_x2t(unsigned& r0, unsigned& r1, const void* p) {
    unsigned a = (unsigned)__cvta_generic_to_shared(p);
    asm volatile("ldmatrix.sync.aligned.m8n8.x2.trans.shared.b16 {%0,%1}, [%2];\n"
                 : "=r"(r0), "=r"(r1) : "r"(a));
}
#define MMA16816(d, a, bf)                                                              \
    asm volatile(                                                                       \
        "mma.sync.aligned.m16n8k16.row.col.f32.f16.f16.f32 "                            \
        "{%0,%1,%2,%3},{%4,%5,%6,%7},{%8,%9},{%0,%1,%2,%3};\n"                          \
        : "+f"(d[0]), "+f"(d[1]), "+f"(d[2]), "+f"(d[3])                                \
        : "r"(a[0]), "r"(a[1]), "r"(a[2]), "r"(a[3]), "r"(bf[0]), "r"(bf[1]))

__global__ void __launch_bounds__(256) k_gemm(const int* __restrict__ bm,
                                              float* __restrict__ out) {
    __shared__ __align__(16) __half As[2][128][40];   // [c_local][k_local]
    __shared__ __align__(16) __half Bs[2][32][136];   // [k_local][q_local]

    int tid  = threadIdx.x;
    int warp = tid >> 5, lane = tid & 31;
    int n  = blockIdx.z;
    int b  = bm[n] & (cB - 1);   // values in [0,B); mask guards garbage
    int q0 = blockIdx.x * 128;
    int c0 = blockIdx.y * 128;

    int wm = (warp >> 2) * 64;   // warp row offset (M)
    int wn = (warp & 3) * 32;    // warp col offset (N)

    const __half* Abase = g_V + ((size_t)n * cCV + c0) * cTHW;
    const __half* Bbase = g_P + (size_t)b * cTHW * cHWP + q0;

    auto load = [&](int kt, int buf) {
#pragma unroll
        for (int j = 0; j < 2; j++) {
            int id = tid + j * 256;            // 0..511
            int r  = id >> 2;                  // 0..127
            int cc = (id & 3) * 8;             // 0..24
            cpasync16(&As[buf][r][cc], Abase + (size_t)r * cTHW + kt * 32 + cc);
        }
#pragma unroll
        for (int j = 0; j < 2; j++) {
            int id = tid + j * 256;
            int r  = id >> 4;                  // 0..31
            int cc = (id & 15) * 8;            // 0..120
            cpasync16(&Bs[buf][r][cc], Bbase + (size_t)(kt * 32 + r) * cHWP + cc);
        }
    };

    float acc[4][4][4];
#pragma unroll
    for (int mf = 0; mf < 4; mf++)
#pragma unroll
        for (int nf = 0; nf < 4; nf++)
#pragma unroll
            for (int k = 0; k < 4; k++) acc[mf][nf][k] = 0.f;

    load(0, 0);
    asm volatile("cp.async.commit_group;\n");

    for (int kt = 0; kt < KT; kt++) {
        int cur = kt & 1;
        if (kt + 1 < KT) load(kt + 1, cur ^ 1);
        asm volatile("cp.async.commit_group;\n");
        asm volatile("cp.async.wait_group 1;\n" ::: "memory");
        __syncthreads();

#pragma unroll
        for (int ks = 0; ks < 2; ks++) {
            unsigned af[4][4];
            unsigned bf[4][2];
#pragma unroll
            for (int mf = 0; mf < 4; mf++)
                ldsm_x4(af[mf][0], af[mf][1], af[mf][2], af[mf][3],
                        &As[cur][wm + mf * 16 + (lane & 15)][ks * 16 + (lane >> 4) * 8]);
#pragma unroll
            for (int nf = 0; nf < 4; nf++)
                ldsm_x2t(bf[nf][0], bf[nf][1],
                         &Bs[cur][ks * 16 + (lane & 15)][wn + nf * 8]);
#pragma unroll
            for (int mf = 0; mf < 4; mf++)
#pragma unroll
                for (int nf = 0; nf < 4; nf++) MMA16816(acc[mf][nf], af[mf], bf[nf]);
        }
        __syncthreads();
    }

    // epilogue: out = acc * invZ[q]
    int gr = lane >> 2;
    int gc = (lane & 3) * 2;
#pragma unroll
    for (int nf = 0; nf < 4; nf++) {
        int q = q0 + wn + nf * 8 + gc;
        if (q < cHW) {
            float iz0 = g_Z[b * cHW + q];
            float iz1 = g_Z[b * cHW + q + 1];
#pragma unroll
            for (int mf = 0; mf < 4; mf++) {
                int r = c0 + wm + mf * 16 + gr;
                float* o = out + ((size_t)n * cCV + r) * cHW + q;
                o[0] = acc[mf][nf][0] * iz0;
                o[1] = acc[mf][nf][1] * iz1;
                float* o2 = o + 8 * cHW;
                o2[0] = acc[mf][nf][2] * iz0;
                o2[1] = acc[mf][nf][3] * iz1;
            }
        }
    }
}

// ---------------- launch ----------------
extern "C" void kernel_launch(void* const* d_in, const int* in_sizes, int n_in,
                              void* d_out, int out_size) {
    const float* mk  = (const float*)d_in[0];
    const float* mv  = (const float*)d_in[1];
    const float* qkp = (const float*)d_in[2];
    const int*   bm  = (const int*)d_in[3];   // jax x64 disabled -> int32, not int64
    float* out       = (float*)d_out;

    k_init<<<(cB * cHW + 255) / 256, 256>>>();
    k_asq<<<(cB * cTHW + 255) / 256, 256>>>(mk);
    k_vconv<<<2048, 256>>>(mv);
    k_logits<<<dim3((cHW + 63) / 64, (cTHW + 63) / 64, cB), 256>>>(mk, qkp);
    k_expsum<<<dim3((cHW + 255) / 256, cZCH, cB), 256>>>();
    k_zred<<<(cB * cHW + 255) / 256, 256>>>();
    k_gemm<<<dim3((cHW + 127) / 128, cCV / 128, cN), 256>>>(bm, out);
}

// round 3
// speedup vs baseline: 1.0393x; 1.0393x over previous
#include <cuda_runtime.h>
#include <cuda_fp16.h>

// ---------------- problem constants ----------------
constexpr int cB   = 4;
constexpr int cCK  = 64;
constexpr int cTHW = 12960;   // 8*30*54
constexpr int cHW  = 1620;    // 30*54
constexpr int cN   = 8;
constexpr int cCV  = 512;
constexpr int cHWP = 1632;    // padded P row stride (16B-aligned rows for cp.async)
constexpr int cZCH = 24;      // chunks for deterministic Z reduction (12960/24=540)
constexpr int KT   = cTHW / 32;  // 405 k-tiles in readout GEMM

// ---------------- scratch (device globals: allocation-free) ----------------
__device__ float                g_S[(size_t)cB * cTHW * cHW];            // logits fp32
__device__ __align__(16) __half g_P[(size_t)cB * cTHW * cHWP + 4096];    // exp(s-M) fp16, padded
__device__ __align__(16) __half g_V[(size_t)cN * cCV * cTHW];            // values fp16
__device__ __align__(16) __half g_mkhi[(size_t)cB * cTHW * cCK];         // mk hi, [b][t][c]
__device__ __align__(16) __half g_mklo[(size_t)cB * cTHW * cCK];         // mk lo
__device__ __align__(16) __half g_qkhi[(size_t)cB * cHW * cCK];          // qk hi, [b][q][c]
__device__ __align__(16) __half g_qklo[(size_t)cB * cHW * cCK];          // qk lo
__device__ float                g_asq[cB * cTHW];
__device__ unsigned             g_M[cB * cHW];                           // column max, encoded key
__device__ float                g_Zp[cB * cZCH * cHW];                   // Z partials (deterministic)
__device__ float                g_Z[cB * cHW];                           // 1/Z

// order-preserving float <-> uint key (for exact, order-independent atomic max)
__device__ __forceinline__ unsigned fenc(float f) {
    unsigned u = __float_as_uint(f);
    return (u & 0x80000000u) ? ~u : (u | 0x80000000u);
}
__device__ __forceinline__ float fdec(unsigned k) {
    unsigned u = (k & 0x80000000u) ? (k ^ 0x80000000u) : ~k;
    return __uint_as_float(u);
}
__device__ __forceinline__ unsigned hpack(__half a, __half b) {
    return (unsigned)__half_as_ushort(a) | ((unsigned)__half_as_ushort(b) << 16);
}

// ---------------- k_init: reset column-max keys ----------------
__global__ void k_init() {
    int i = blockIdx.x * blockDim.x + threadIdx.x;
    if (i < cB * cHW) g_M[i] = 0u;  // below any real encoded key
}

// ---------------- k_split: mk -> (hi,lo) transposed [b][t][c], fused asq ----------------
__global__ void k_split(const float* __restrict__ mk) {
    int i = blockIdx.x * blockDim.x + threadIdx.x;
    if (i >= cB * cTHW) return;
    int b = i / cTHW;
    int t = i - b * cTHW;
    const float* p = mk + (size_t)b * cCK * cTHW + t;

    unsigned hb[32], lb[32];
    float s = 0.f;
#pragma unroll
    for (int c = 0; c < cCK; c += 2) {
        float v0 = p[(size_t)c * cTHW];
        float v1 = p[(size_t)(c + 1) * cTHW];
        s = fmaf(v0, v0, s);
        s = fmaf(v1, v1, s);
        __half h0 = __float2half_rn(v0), h1 = __float2half_rn(v1);
        float l0 = v0 - __half2float(h0), l1 = v1 - __half2float(h1);
        hb[c >> 1] = hpack(h0, h1);
        lb[c >> 1] = hpack(__float2half_rn(l0), __float2half_rn(l1));
    }
    g_asq[i] = s;
    uint4* dh = (uint4*)(g_mkhi + (size_t)i * cCK);
    uint4* dl = (uint4*)(g_mklo + (size_t)i * cCK);
#pragma unroll
    for (int j = 0; j < 8; j++) {
        dh[j] = make_uint4(hb[4 * j], hb[4 * j + 1], hb[4 * j + 2], hb[4 * j + 3]);
        dl[j] = make_uint4(lb[4 * j], lb[4 * j + 1], lb[4 * j + 2], lb[4 * j + 3]);
    }
}

// ---------------- k_splitq: qk -> (hi,lo) transposed [b][q][c] ----------------
__global__ void k_splitq(const float* __restrict__ qk) {
    int i = blockIdx.x * blockDim.x + threadIdx.x;
    if (i >= cB * cHW) return;
    int b = i / cHW;
    int q = i - b * cHW;
    const float* p = qk + (size_t)b * cCK * cHW + q;

    unsigned hb[32], lb[32];
#pragma unroll
    for (int c = 0; c < cCK; c += 2) {
        float v0 = p[(size_t)c * cHW];
        float v1 = p[(size_t)(c + 1) * cHW];
        __half h0 = __float2half_rn(v0), h1 = __float2half_rn(v1);
        float l0 = v0 - __half2float(h0), l1 = v1 - __half2float(h1);
        hb[c >> 1] = hpack(h0, h1);
        lb[c >> 1] = hpack(__float2half_rn(l0), __float2half_rn(l1));
    }
    uint4* dh = (uint4*)(g_qkhi + (size_t)i * cCK);
    uint4* dl = (uint4*)(g_qklo + (size_t)i * cCK);
#pragma unroll
    for (int j = 0; j < 8; j++) {
        dh[j] = make_uint4(hb[4 * j], hb[4 * j + 1], hb[4 * j + 2], hb[4 * j + 3]);
        dl[j] = make_uint4(lb[4 * j], lb[4 * j + 1], lb[4 * j + 2], lb[4 * j + 3]);
    }
}

// ---------------- k_vconv: mem_values fp32 -> fp16 ----------------
__global__ void k_vconv(const float* __restrict__ v) {
    size_t n4 = (size_t)cN * cCV * cTHW / 4;
    for (size_t i = (size_t)blockIdx.x * blockDim.x + threadIdx.x; i < n4;
         i += (size_t)gridDim.x * blockDim.x) {
        float4 f = ((const float4*)v)[i];
        __half2 h0 = __floats2half2_rn(f.x, f.y);
        __half2 h1 = __floats2half2_rn(f.z, f.w);
        ((__half2*)g_V)[2 * i]     = h0;
        ((__half2*)g_V)[2 * i + 1] = h1;
    }
}

// ---------------- mma helpers ----------------
__device__ __forceinline__ void ldsm_x4(unsigned& r0, unsigned& r1, unsigned& r2, unsigned& r3,
                                        const void* p) {
    unsigned a = (unsigned)__cvta_generic_to_shared(p);
    asm volatile("ldmatrix.sync.aligned.m8n8.x4.shared.b16 {%0,%1,%2,%3}, [%4];\n"
                 : "=r"(r0), "=r"(r1), "=r"(r2), "=r"(r3) : "r"(a));
}
__device__ __forceinline__ void ldsm_x2(unsigned& r0, unsigned& r1, const void* p) {
    unsigned a = (unsigned)__cvta_generic_to_shared(p);
    asm volatile("ldmatrix.sync.aligned.m8n8.x2.shared.b16 {%0,%1}, [%2];\n"
                 : "=r"(r0), "=r"(r1) : "r"(a));
}
__device__ __forceinline__ void ldsm_x2t(unsigned& r0, unsigned& r1, const void* p) {
    unsigned a = (unsigned)__cvta_generic_to_shared(p);
    asm volatile("ldmatrix.sync.aligned.m8n8.x2.trans.shared.b16 {%0,%1}, [%2];\n"
                 : "=r"(r0), "=r"(r1) : "r"(a));
}
#define MMA16816(d, a, bf)                                                              \
    asm volatile(                                                                       \
        "mma.sync.aligned.m16n8k16.row.col.f32.f16.f16.f32 "                            \
        "{%0,%1,%2,%3},{%4,%5,%6,%7},{%8,%9},{%0,%1,%2,%3};\n"                          \
        : "+f"(d[0]), "+f"(d[1]), "+f"(d[2]), "+f"(d[3])                                \
        : "r"(a[0]), "r"(a[1]), "r"(a[2]), "r"(a[3]), "r"(bf[0]), "r"(bf[1]))

// ---------------- k_logits_mma: S = 0.25*(hi*hi + hi*lo + lo*hi) - 0.125*asq ----------------
// tile 128(t) x 128(q), K=64, split-fp16 tensor GEMM + fused column max
constexpr int LPAD = 72;  // row stride (halves): 144B -> conflict-free ldmatrix
__global__ void __launch_bounds__(256) k_logits_mma() {
    extern __shared__ __half lsm[];
    __half* Ah = lsm;
    __half* Al = lsm + 128 * LPAD;
    __half* Bh = lsm + 2 * 128 * LPAD;
    __half* Bl = lsm + 3 * 128 * LPAD;
    __shared__ unsigned smax[128];

    int tid = threadIdx.x, lane = tid & 31, warp = tid >> 5;
    int b = blockIdx.z;
    int t0 = blockIdx.y * 128;
    int q0 = blockIdx.x * 128;
    if (tid < 128) smax[tid] = 0u;

    const __half* mkh = g_mkhi + ((size_t)b * cTHW + t0) * cCK;
    const __half* mkl = g_mklo + ((size_t)b * cTHW + t0) * cCK;
    const __half* qh  = g_qkhi + ((size_t)b * cHW + q0) * cCK;
    const __half* ql  = g_qklo + ((size_t)b * cHW + q0) * cCK;

#pragma unroll
    for (int j = 0; j < 4; j++) {
        int id = tid + j * 256;         // 0..1023
        int r  = id >> 3;               // 0..127
        int cc = (id & 7) * 8;          // 0..56
        uint4 z = make_uint4(0, 0, 0, 0);
        uint4 vh = z, vl = z, wh = z, wl = z;
        if (t0 + r < cTHW) {
            vh = *(const uint4*)(mkh + (size_t)r * cCK + cc);
            vl = *(const uint4*)(mkl + (size_t)r * cCK + cc);
        }
        *(uint4*)(Ah + r * LPAD + cc) = vh;
        *(uint4*)(Al + r * LPAD + cc) = vl;
        if (q0 + r < cHW) {
            wh = *(const uint4*)(qh + (size_t)r * cCK + cc);
            wl = *(const uint4*)(ql + (size_t)r * cCK + cc);
        }
        *(uint4*)(Bh + r * LPAD + cc) = wh;
        *(uint4*)(Bl + r * LPAD + cc) = wl;
    }
    __syncthreads();

    int wm = (warp >> 2) * 64;
    int wn = (warp & 3) * 32;

    float acc[4][4][4];
#pragma unroll
    for (int mf = 0; mf < 4; mf++)
#pragma unroll
        for (int nf = 0; nf < 4; nf++)
#pragma unroll
            for (int k = 0; k < 4; k++) acc[mf][nf][k] = 0.f;

#pragma unroll
    for (int kk = 0; kk < 4; kk++) {
        unsigned ah[4][4], al[4][4], bh[4][2], bl[4][2];
        int ac = kk * 16 + (lane >> 4) * 8;
#pragma unroll
        for (int mf = 0; mf < 4; mf++) {
            int ar = wm + mf * 16 + (lane & 15);
            ldsm_x4(ah[mf][0], ah[mf][1], ah[mf][2], ah[mf][3], Ah + ar * LPAD + ac);
            ldsm_x4(al[mf][0], al[mf][1], al[mf][2], al[mf][3], Al + ar * LPAD + ac);
        }
        int bc = kk * 16 + ((lane >> 3) & 1) * 8;
#pragma unroll
        for (int nf = 0; nf < 4; nf++) {
            int br = wn + nf * 8 + (lane & 7);
            ldsm_x2(bh[nf][0], bh[nf][1], Bh + br * LPAD + bc);
            ldsm_x2(bl[nf][0], bl[nf][1], Bl + br * LPAD + bc);
        }
#pragma unroll
        for (int mf = 0; mf < 4; mf++)
#pragma unroll
            for (int nf = 0; nf < 4; nf++) {
                MMA16816(acc[mf][nf], ah[mf], bh[nf]);
                MMA16816(acc[mf][nf], ah[mf], bl[nf]);
                MMA16816(acc[mf][nf], al[mf], bh[nf]);
            }
    }

    // epilogue: S = 0.25*acc - 0.125*asq, store + column max
    int r0 = lane >> 2;
    int cl = (lane & 3) * 2;
#pragma unroll
    for (int nf = 0; nf < 4; nf++) {
        int q = q0 + wn + nf * 8 + cl;
        bool qok = (q < cHW);   // q even, cHW even -> covers q+1 too
        float mx0 = -3.4e38f, mx1 = -3.4e38f;
#pragma unroll
        for (int mf = 0; mf < 4; mf++) {
            int t1 = t0 + wm + mf * 16 + r0;
            int t2 = t1 + 8;
            float asq0 = (t1 < cTHW) ? g_asq[b * cTHW + t1] : 0.f;
            float asq1 = (t2 < cTHW) ? g_asq[b * cTHW + t2] : 0.f;
            float s0 = 0.25f * acc[mf][nf][0] - 0.125f * asq0;
            float s1 = 0.25f * acc[mf][nf][1] - 0.125f * asq0;
            float s2 = 0.25f * acc[mf][nf][2] - 0.125f * asq1;
            float s3 = 0.25f * acc[mf][nf][3] - 0.125f * asq1;
            if (qok) {
                if (t1 < cTHW) {
                    *(float2*)(g_S + ((size_t)b * cTHW + t1) * cHW + q) = make_float2(s0, s1);
                    mx0 = fmaxf(mx0, s0);
                    mx1 = fmaxf(mx1, s1);
                }
                if (t2 < cTHW) {
                    *(float2*)(g_S + ((size_t)b * cTHW + t2) * cHW + q) = make_float2(s2, s3);
                    mx0 = fmaxf(mx0, s2);
                    mx1 = fmaxf(mx1, s3);
                }
            }
        }
        if (qok) {
            atomicMax(&smax[wn + nf * 8 + cl],     fenc(mx0));
            atomicMax(&smax[wn + nf * 8 + cl + 1], fenc(mx1));
        }
    }
    __syncthreads();
    if (tid < 128 && q0 + tid < cHW) atomicMax(&g_M[b * cHW + q0 + tid], smax[tid]);
}

// ---------------- k_expsum: P = fp16(exp(s - M)); deterministic Z partials ----------------
__global__ void k_expsum() {
    int q = blockIdx.x * blockDim.x + threadIdx.x;
    if (q >= cHW) return;
    int b  = blockIdx.z;
    int ch = blockIdx.y;
    constexpr int CHN = cTHW / cZCH;  // 540
    int t0 = ch * CHN;

    float Mv = fdec(g_M[b * cHW + q]);
    const float* Sp = g_S + ((size_t)b * cTHW + t0) * cHW + q;
    __half* Pp      = g_P + ((size_t)b * cTHW + t0) * cHWP + q;

    float z = 0.f;
#pragma unroll 4
    for (int i = 0; i < CHN; i++) {
        float e = __expf(Sp[(size_t)i * cHW] - Mv);
        z += e;
        Pp[(size_t)i * cHWP] = __float2half_rn(e);
    }
    g_Zp[(b * cZCH + ch) * cHW + q] = z;
}

// ---------------- k_zred: invZ ----------------
__global__ void k_zred() {
    int i = blockIdx.x * blockDim.x + threadIdx.x;
    if (i >= cB * cHW) return;
    int b = i / cHW, q = i - b * cHW;
    float s = 0.f;
#pragma unroll
    for (int ch = 0; ch < cZCH; ch++) s += g_Zp[(b * cZCH + ch) * cHW + q];
    g_Z[i] = 1.0f / s;
}

// ---------------- k_gemm: out[n] = V16[n] @ P16[bm[n]] * invZ (3-stage cp.async) ----------------
__device__ __forceinline__ void cpasync16(void* dst, const void* src) {
    unsigned s = (unsigned)__cvta_generic_to_shared(dst);
    asm volatile("cp.async.cg.shared.global [%0], [%1], 16;\n" :: "r"(s), "l"(src));
}

constexpr int ASTG = 128 * 40;   // halves per A stage
constexpr int BSTG = 32 * 136;   // halves per B stage
constexpr int GEMM_SMEM = 3 * (ASTG + BSTG) * 2;  // bytes = 56832

__global__ void __launch_bounds__(256) k_gemm(const int* __restrict__ bm,
                                              float* __restrict__ out) {
    extern __shared__ __half gsm[];
    __half* Asb = gsm;                 // stage s: Asb + s*ASTG, [r][40]
    __half* Bsb = gsm + 3 * ASTG;      // stage s: Bsb + s*BSTG, [r][136]

    int tid  = threadIdx.x;
    int warp = tid >> 5, lane = tid & 31;
    int n  = blockIdx.z;
    int b  = bm[n] & (cB - 1);
    int q0 = blockIdx.x * 128;
    int c0 = blockIdx.y * 128;

    int wm = (warp >> 2) * 64;
    int wn = (warp & 3) * 32;

    const __half* Abase = g_V + ((size_t)n * cCV + c0) * cTHW;
    const __half* Bbase = g_P + (size_t)b * cTHW * cHWP + q0;

    auto load = [&](int kt, int buf) {
        __half* A = Asb + buf * ASTG;
        __half* B = Bsb + buf * BSTG;
#pragma unroll
        for (int j = 0; j < 2; j++) {
            int id = tid + j * 256;            // 0..511
            int r  = id >> 2;                  // 0..127
            int cc = (id & 3) * 8;             // 0..24
            cpasync16(A + r * 40 + cc, Abase + (size_t)r * cTHW + kt * 32 + cc);
        }
#pragma unroll
        for (int j = 0; j < 2; j++) {
            int id = tid + j * 256;
            int r  = id >> 4;                  // 0..31
            int cc = (id & 15) * 8;            // 0..120
            cpasync16(B + r * 136 + cc, Bbase + (size_t)(kt * 32 + r) * cHWP + cc);
        }
    };

    float acc[4][4][4];
#pragma unroll
    for (int mf = 0; mf < 4; mf++)
#pragma unroll
        for (int nf = 0; nf < 4; nf++)
#pragma unroll
            for (int k = 0; k < 4; k++) acc[mf][nf][k] = 0.f;

    load(0, 0);
    asm volatile("cp.async.commit_group;\n");
    load(1, 1);
    asm volatile("cp.async.commit_group;\n");

    for (int kt = 0; kt < KT; kt++) {
        if (kt + 2 < KT) load(kt + 2, (kt + 2) % 3);
        asm volatile("cp.async.commit_group;\n");
        asm volatile("cp.async.wait_group 2;\n" ::: "memory");
        __syncthreads();

        int cur = kt % 3;
        const __half* A = Asb + cur * ASTG;
        const __half* B = Bsb + cur * BSTG;
#pragma unroll
        for (int ks = 0; ks < 2; ks++) {
            unsigned af[4][4];
            unsigned bf[4][2];
#pragma unroll
            for (int mf = 0; mf < 4; mf++)
                ldsm_x4(af[mf][0], af[mf][1], af[mf][2], af[mf][3],
                        A + (wm + mf * 16 + (lane & 15)) * 40 + ks * 16 + (lane >> 4) * 8);
#pragma unroll
            for (int nf = 0; nf < 4; nf++)
                ldsm_x2t(bf[nf][0], bf[nf][1],
                         B + (ks * 16 + (lane & 15)) * 136 + wn + nf * 8);
#pragma unroll
            for (int mf = 0; mf < 4; mf++)
#pragma unroll
                for (int nf = 0; nf < 4; nf++) MMA16816(acc[mf][nf], af[mf], bf[nf]);
        }
        __syncthreads();
    }

    // epilogue: out = acc * invZ[q]
    int gr = lane >> 2;
    int gc = (lane & 3) * 2;
#pragma unroll
    for (int nf = 0; nf < 4; nf++) {
        int q = q0 + wn + nf * 8 + gc;
        if (q < cHW) {
            float iz0 = g_Z[b * cHW + q];
            float iz1 = g_Z[b * cHW + q + 1];
#pragma unroll
            for (int mf = 0; mf < 4; mf++) {
                int r = c0 + wm + mf * 16 + gr;
                float* o = out + ((size_t)n * cCV + r) * cHW + q;
                o[0] = acc[mf][nf][0] * iz0;
                o[1] = acc[mf][nf][1] * iz1;
                float* o2 = o + 8 * cHW;
                o2[0] = acc[mf][nf][2] * iz0;
                o2[1] = acc[mf][nf][3] * iz1;
            }
        }
    }
}

// ---------------- launch ----------------
extern "C" void kernel_launch(void* const* d_in, const int* in_sizes, int n_in,
                              void* d_out, int out_size) {
    const float* mk  = (const float*)d_in[0];
    const float* mv  = (const float*)d_in[1];
    const float* qkp = (const float*)d_in[2];
    const int*   bm  = (const int*)d_in[3];   // jax x64 disabled -> int32
    float* out       = (float*)d_out;

    constexpr int LOGITS_SMEM = 4 * 128 * LPAD * 2;  // 73728 bytes
    cudaFuncSetAttribute(k_logits_mma, cudaFuncAttributeMaxDynamicSharedMemorySize, LOGITS_SMEM);
    cudaFuncSetAttribute(k_gemm, cudaFuncAttributeMaxDynamicSharedMemorySize, GEMM_SMEM);

    k_init<<<(cB * cHW + 255) / 256, 256>>>();
    k_split<<<(cB * cTHW + 255) / 256, 256>>>(mk);
    k_splitq<<<(cB * cHW + 255) / 256, 256>>>(qkp);
    k_vconv<<<2048, 256>>>(mv);
    k_logits_mma<<<dim3((cHW + 127) / 128, (cTHW + 127) / 128, cB), 256, LOGITS_SMEM>>>();
    k_expsum<<<dim3((cHW + 255) / 256, cZCH, cB), 256>>>();
    k_zred<<<(cB * cHW + 255) / 256, 256>>>();
    k_gemm<<<dim3((cHW + 127) / 128, cCV / 128, cN), 256, GEMM_SMEM>>>(bm, out);
}